// round 3
// baseline (speedup 1.0000x reference)
#include <cuda_runtime.h>
#include <cstdint>

// Zero-initialized device globals (no allocations allowed).
// g_flags bit0: any(((x+1)+1) >= 3)          -> chain halts after checker #1; out = x+1+1 (speculative write is correct)
// g_flags bit1: any((((((x+1)+1)+1)+1)) >= 3)-> chain halts after checker #2; out = four adds
// neither     : out = five adds
// Both are reset by the last-arriving block each call, so the kernel is
// deterministic across graph replays.
__device__ int g_flags;
__device__ unsigned int g_count;

__global__ void __launch_bounds__(512) scn_fused_kernel(
    const float4* __restrict__ x, float4* __restrict__ out, int n4)
{
    const int idx    = blockIdx.x * blockDim.x + threadIdx.x;
    const int stride = gridDim.x * blockDim.x;

    bool a = false;  // any((x+1)+1 >= 3)
    bool b = false;  // any(four-adds >= 3)

    for (int i = idx; i < n4; i += stride) {
        float4 v = x[i];
        // Sequential adds — bit-exact vs the reference chain.
        float4 o;
        o.x = (v.x + 1.0f) + 1.0f;
        o.y = (v.y + 1.0f) + 1.0f;
        o.z = (v.z + 1.0f) + 1.0f;
        o.w = (v.w + 1.0f) + 1.0f;

        float m2 = fmaxf(fmaxf(o.x, o.y), fmaxf(o.z, o.w));
        a |= (m2 >= 3.0f);

        float qx = (o.x + 1.0f) + 1.0f;
        float qy = (o.y + 1.0f) + 1.0f;
        float qz = (o.z + 1.0f) + 1.0f;
        float qw = (o.w + 1.0f) + 1.0f;
        float m4 = fmaxf(fmaxf(qx, qy), fmaxf(qz, qw));
        b |= (m4 >= 3.0f);

        out[i] = o;
    }

    // Block-level any-reduction.
    int any_a = __syncthreads_or(a ? 1 : 0);
    int any_b = __syncthreads_or(b ? 1 : 0);

    // Make this block's out[] writes device-visible before signalling arrival.
    __threadfence();
    __syncthreads();

    __shared__ int s_last;
    if (threadIdx.x == 0) {
        int f = (any_a ? 1 : 0) | (any_b ? 2 : 0);
        if (f) atomicOr(&g_flags, f);
        __threadfence();  // order flag OR before arrival increment
        unsigned t = atomicAdd(&g_count, 1u);
        s_last = (t == gridDim.x - 1) ? 1 : 0;
    }
    __syncthreads();

    if (s_last) {
        // Last-arriving block: every other block's flags + writes are visible.
        int f = atomicOr(&g_flags, 0);  // L2-coherent read

        if (!(f & 1)) {
            // Rare path (never taken for N(0,1) input of this size): the chain
            // survived the first checker, so rewrite the whole output with the
            // deeper-chain values. Single block — slow but correct.
            bool five = !(f & 2);
            for (int i = threadIdx.x; i < n4; i += blockDim.x) {
                float4 v = x[i];
                float4 o;
                o.x = (((v.x + 1.0f) + 1.0f) + 1.0f) + 1.0f;
                o.y = (((v.y + 1.0f) + 1.0f) + 1.0f) + 1.0f;
                o.z = (((v.z + 1.0f) + 1.0f) + 1.0f) + 1.0f;
                o.w = (((v.w + 1.0f) + 1.0f) + 1.0f) + 1.0f;
                if (five) { o.x += 1.0f; o.y += 1.0f; o.z += 1.0f; o.w += 1.0f; }
                out[i] = o;
            }
        }

        __syncthreads();
        if (threadIdx.x == 0) {
            // Reset globals for the next graph replay. All arrivals already
            // happened (we were last), so no same-call race.
            g_flags = 0;
            __threadfence();
            g_count = 0u;
        }
    }
}

extern "C" void kernel_launch(void* const* d_in, const int* in_sizes, int n_in,
                              void* d_out, int out_size)
{
    const float4* x = (const float4*)d_in[0];
    float4* out = (float4*)d_out;
    int n = in_sizes[0];
    int n4 = n >> 2;  // 4096*8192 divisible by 4

    const int threads = 512;
    const int blocks  = 148 * 4;  // one full wave at 2048 thr/SM

    scn_fused_kernel<<<blocks, threads>>>(x, out, n4);
}